// round 14
// baseline (speedup 1.0000x reference)
#include <cuda_runtime.h>
#include <cstdint>

#define CH_IN 32
#define CH_Y  16
#define IMG_H 256
#define IMG_W 256
#define NB    16
#define CHS   (IMG_H * IMG_W)   // channel stride (elements)
#define CHS4  (CHS / 4)
#define CHS2  (CHS / 2)
#define NT    128               // thread: H=tid&1 (o-half), g=tid>>1 (4-px group)

union F2U { float2 f; uint64_t u; };

// sm_103a packed dual-fp32 ops
__device__ __forceinline__ void fma2(uint64_t& d, uint64_t a, uint64_t b) {
    asm("fma.rn.f32x2 %0, %1, %2, %0;" : "+l"(d) : "l"(a), "l"(b));
}
__device__ __forceinline__ uint64_t mul2(uint64_t a, uint64_t b) {
    uint64_t d; asm("mul.rn.f32x2 %0, %1, %2;" : "=l"(d) : "l"(a), "l"(b)); return d;
}
__device__ __forceinline__ uint64_t add2(uint64_t a, uint64_t b) {
    uint64_t d; asm("add.rn.f32x2 %0, %1, %2;" : "=l"(d) : "l"(a), "l"(b)); return d;
}
__device__ __forceinline__ uint64_t dup2(float x) {
    uint64_t d; asm("mov.b64 %0, {%1, %1};" : "=l"(d) : "f"(x)); return d;
}
__device__ __forceinline__ uint64_t pack2(float lo, float hi) {
    uint64_t d; asm("mov.b64 %0, {%1, %2};" : "=l"(d) : "f"(lo), "f"(hi)); return d;
}

// R6 skeleton + 4px/thread with lane-paired o-split:
//   thread (g, H): pixels w = 4g..4g+3, output channels o in [8H, 8H+8).
// Adjacent lanes (H=0/1) duplicate input addresses -> L1 dedups (input wf
// unchanged vs R6) while weight LDS per thread halves. qk packed (q_o,k_o)
// via interleaved qkT layout; v/e packed over o-pairs; y-exchange in the
// dead p-staging smem; conv split by pixel so wy stays broadcast.
__global__ void __launch_bounds__(NT, 4) cross_attn_kernel(
    const float* __restrict__ cin, const float* __restrict__ pin,
    const float* __restrict__ Wq,  const float* __restrict__ bq,
    const float* __restrict__ Wk,  const float* __restrict__ bk,
    const float* __restrict__ Wv,  const float* __restrict__ bv,
    const float* __restrict__ Wy,  const float* __restrict__ by,
    float* __restrict__ out)
{
    __shared__ float4 sp4[CH_IN * IMG_W / 4];        // 32KB p row; ybuf overlay
    __shared__ __align__(16) float2 qkT[CH_IN * CH_Y];  // [ch][o]=(Wq[o][ch],Wk[o][ch]) 4KB
    __shared__ __align__(16) float2 vT [CH_IN * 8];     // [ch][o2] natural o-pairs 2KB
    __shared__ __align__(16) float4 wy_s[CH_IN * CH_Y / 4];
    __shared__ float2   bqk_s[CH_Y];                 // (bq[o], bk[o])
    __shared__ float2   bv2[8];
    __shared__ float    by_s[CH_IN];
    __shared__ uint64_t red[4][2][4];                // [warp][H][olp]

    const int tid = threadIdx.x;
    const int H   = tid & 1;          // o-half
    const int g   = tid >> 1;         // 4-px group, 0..63

    // ---- weight setup ----
#pragma unroll
    for (int s = 0; s < 4; s++) {     // qkT: 512 entries
        int i = tid * 4 + s;
        int ch = i >> 4, o = i & 15;
        qkT[i] = make_float2(Wq[o * CH_IN + ch], Wk[o * CH_IN + ch]);
    }
#pragma unroll
    for (int s = 0; s < 2; s++) {     // vT: 256 entries
        int i = tid * 2 + s;
        int ch = i >> 3, o2 = i & 7;
        vT[i] = make_float2(Wv[(2*o2) * CH_IN + ch], Wv[(2*o2+1) * CH_IN + ch]);
    }
    wy_s[tid] = ((const float4*)Wy)[tid];
    if (tid < CH_Y) bqk_s[tid] = make_float2(bq[tid], bk[tid]);
    if (tid < 8)    bv2[tid]   = make_float2(bv[2*tid], bv[2*tid+1]);
    if (tid < CH_IN) by_s[tid] = by[tid];

    const int h = blockIdx.x & (IMG_H - 1);
    const int b = blockIdx.x >> 8;
    const size_t base = (size_t)b * CH_IN * CHS + (size_t)h * IMG_W;

    const float4* cg = (const float4*)(cin + base);
    const float4* pg = (const float4*)(pin + base);
    float4* oyg = (float4*)(out + (size_t)b * 2 * CH_IN * CHS + (size_t)h * IMG_W);
    float4* ocg = oyg + (size_t)CH_IN * CHS4;        // concat(c) half

    // ---------------- Phase 1: stage p + concat copy of c ----------------
#pragma unroll
    for (int halfb = 0; halfb < 2; halfb++) {
        float4 cb[8], pb[8];
#pragma unroll
        for (int i = 0; i < 8; i++) {
            int idx = tid + (halfb * 8 + i) * NT;    // = ch*64 + w4
            int ch = idx >> 6, w4 = idx & 63;
            cb[i] = cg[(size_t)ch * CHS4 + w4];
            pb[i] = pg[(size_t)ch * CHS4 + w4];
        }
#pragma unroll
        for (int i = 0; i < 8; i++) {
            int idx = tid + (halfb * 8 + i) * NT;
            int ch = idx >> 6, w4 = idx & 63;
            ocg[(size_t)ch * CHS4 + w4] = cb[i];
            sp4[idx] = pb[i];
        }
    }
    __syncthreads();

    // ------------- fused q,k projection: qk[px][o_local] = (q,k) -------------
    uint64_t qk[4][8];
#pragma unroll
    for (int o = 0; o < 8; o++) {
        F2U t; t.f = bqk_s[8 * H + o];
#pragma unroll
        for (int px = 0; px < 4; px++) qk[px][o] = t.u;
    }

#pragma unroll
    for (int c2 = 0; c2 < CH_IN / 2; c2++) {         // 2 channels per step
        float4 cf[2], pf[2];
#pragma unroll
        for (int j = 0; j < 2; j++) {
            int ch = c2 * 2 + j;
            cf[j] = cg[(size_t)ch * CHS4 + g];       // L2-resident (pair-dup lanes)
            pf[j] = sp4[ch * 64 + g];
        }
#pragma unroll
        for (int j = 0; j < 2; j++) {
            const int ch = c2 * 2 + j;
            const ulonglong2* wq = (const ulonglong2*)&qkT[ch * CH_Y + 8 * H];
            uint64_t cp[4] = { pack2(cf[j].x, pf[j].x), pack2(cf[j].y, pf[j].y),
                               pack2(cf[j].z, pf[j].z), pack2(cf[j].w, pf[j].w) };
#pragma unroll
            for (int m = 0; m < 4; m++) {            // o-pairs (2m, 2m+1) local
                ulonglong2 w = wq[m];
#pragma unroll
                for (int px = 0; px < 4; px++) {
                    fma2(qk[px][2*m+0], w.x, cp[px]);
                    fma2(qk[px][2*m+1], w.y, cp[px]);
                }
            }
        }
    }

    // exp(q*k). No max-subtraction: |q*k| O(1..10); fp32 exp safe, identical
    // after normalization. e[px][olp] covers global o2 = 4H+olp.
    uint64_t e[4][4];
#pragma unroll
    for (int px = 0; px < 4; px++)
#pragma unroll
        for (int olp = 0; olp < 4; olp++) {
            F2U a, c2v; a.u = qk[px][2*olp]; c2v.u = qk[px][2*olp+1];
            e[px][olp] = pack2(__expf(a.f.x * a.f.y), __expf(c2v.f.x * c2v.f.y));
        }

    // ---- softmax over width: butterfly over same-parity lanes + smem ----
    const int lane = tid & 31;
    const int wrp  = tid >> 5;
#pragma unroll
    for (int olp = 0; olp < 4; olp++) {
        uint64_t s = add2(add2(e[0][olp], e[1][olp]), add2(e[2][olp], e[3][olp]));
#pragma unroll
        for (int d = 16; d > 1; d >>= 1)             // d=16,8,4,2: same parity
            s = add2(s, __shfl_xor_sync(0xffffffffu, (unsigned long long)s, d));
        if (lane < 2) red[wrp][lane][olp] = s;       // lane0=H0, lane1=H1
    }
    __syncthreads();

#pragma unroll
    for (int olp = 0; olp < 4; olp++) {
        F2U tot; tot.u = add2(add2(red[0][H][olp], red[1][H][olp]),
                              add2(red[2][H][olp], red[3][H][olp]));
        uint64_t inv = pack2(__frcp_rn(tot.f.x), __frcp_rn(tot.f.y));
#pragma unroll
        for (int px = 0; px < 4; px++)
            e[px][olp] = mul2(e[px][olp], inv);      // fold 1/sum into e
    }

    // ---------------- v projection (my o-half), y folded in ----------------
    {
        uint64_t v[4][4];
#pragma unroll
        for (int olp = 0; olp < 4; olp++) {
            F2U t; t.f = bv2[4 * H + olp];
#pragma unroll
            for (int px = 0; px < 4; px++) v[px][olp] = t.u;
        }
#pragma unroll
        for (int c2 = 0; c2 < CH_IN / 2; c2++) {
            float4 pf[2];
#pragma unroll
            for (int j = 0; j < 2; j++)
                pf[j] = sp4[(c2 * 2 + j) * 64 + g];
#pragma unroll
            for (int j = 0; j < 2; j++) {
                const int ch = c2 * 2 + j;
                const ulonglong2* wv = (const ulonglong2*)&vT[ch * 8 + 4 * H];
                uint64_t pd[4] = { dup2(pf[j].x), dup2(pf[j].y),
                                   dup2(pf[j].z), dup2(pf[j].w) };
#pragma unroll
                for (int m = 0; m < 2; m++) {        // olp pairs (2m, 2m+1)
                    ulonglong2 w = wv[m];
#pragma unroll
                    for (int px = 0; px < 4; px++) {
                        fma2(v[px][2*m+0], w.x, pd[px]);
                        fma2(v[px][2*m+1], w.y, pd[px]);
                    }
                }
            }
        }
#pragma unroll
        for (int px = 0; px < 4; px++)
#pragma unroll
            for (int olp = 0; olp < 4; olp++)
                e[px][olp] = mul2(e[px][olp], v[px][olp]);   // y = softmax * v
    }

    // -------- y exchange via smem overlay: ybuf[(o2*4+px)*64+g] --------
    __syncthreads();                  // all p reads complete before overwrite
    uint64_t* ybuf = (uint64_t*)sp4;  // 16KB used
#pragma unroll
    for (int olp = 0; olp < 4; olp++)
#pragma unroll
        for (int px = 0; px < 4; px++)
            ybuf[((4 * H + olp) * 4 + px) * 64 + g] = e[px][olp];
    __syncthreads();

    // my conv pixels: pxl 0,1 -> global px 2H, 2H+1 within group g
    uint64_t ya[2][8];
#pragma unroll
    for (int o2 = 0; o2 < 8; o2++) {
        ya[0][o2] = ybuf[(o2 * 4 + 2 * H + 0) * 64 + g];
        ya[1][o2] = ybuf[(o2 * 4 + 2 * H + 1) * 64 + g];
    }

    // ---------------- output conv1x1: all 32 ic, my 2 px ----------------
    float2* oy2 = (float2*)(out + (size_t)b * 2 * CH_IN * CHS + (size_t)h * IMG_W);
    const ulonglong2* wyu2 = (const ulonglong2*)wy_s;    // 4 per ic (broadcast)
#pragma unroll
    for (int ic = 0; ic < CH_IN; ic++) {
        uint64_t acc0 = pack2(by_s[ic], 0.f);
        uint64_t acc1 = acc0;
#pragma unroll
        for (int m = 0; m < 4; m++) {
            ulonglong2 w = wyu2[ic * 4 + m];             // o2 (2m, 2m+1)
            fma2(acc0, w.x, ya[0][2*m+0]); fma2(acc0, w.y, ya[0][2*m+1]);
            fma2(acc1, w.x, ya[1][2*m+0]); fma2(acc1, w.y, ya[1][2*m+1]);
        }
        F2U r0, r1; r0.u = acc0; r1.u = acc1;
        oy2[(size_t)ic * CHS2 + 2 * g + H] = make_float2(r0.f.x + r0.f.y,
                                                         r1.f.x + r1.f.y);
    }
}

extern "C" void kernel_launch(void* const* d_in, const int* in_sizes, int n_in,
                              void* d_out, int out_size)
{
    cross_attn_kernel<<<NB * IMG_H, NT>>>(
        (const float*)d_in[0],  // c
        (const float*)d_in[1],  // p
        (const float*)d_in[2],  // Wq
        (const float*)d_in[3],  // bq
        (const float*)d_in[4],  // Wk
        (const float*)d_in[5],  // bk
        (const float*)d_in[6],  // Wv
        (const float*)d_in[7],  // bv
        (const float*)d_in[8],  // Wy
        (const float*)d_in[9],  // by
        (float*)d_out);
}

// round 15
// speedup vs baseline: 1.2086x; 1.2086x over previous
#include <cuda_runtime.h>
#include <cstdint>

#define CH_IN 32
#define CH_Y  16
#define IMG_H 256
#define IMG_W 256
#define NB    16
#define CHS   (IMG_H * IMG_W)   // channel stride (elements)
#define CHS2  (CHS / 2)
#define NT    128               // one (b,h) row; thread = px-pair, full 16 o
#define ROWB  (IMG_W * 4)       // bytes per channel strip (1KB)

union F2U { float2 f; uint64_t u; };

// sm_103a packed dual-fp32 ops
__device__ __forceinline__ void fma2(uint64_t& d, uint64_t a, uint64_t b) {
    asm("fma.rn.f32x2 %0, %1, %2, %0;" : "+l"(d) : "l"(a), "l"(b));
}
__device__ __forceinline__ uint64_t mul2(uint64_t a, uint64_t b) {
    uint64_t d; asm("mul.rn.f32x2 %0, %1, %2;" : "=l"(d) : "l"(a), "l"(b)); return d;
}
__device__ __forceinline__ uint64_t add2(uint64_t a, uint64_t b) {
    uint64_t d; asm("add.rn.f32x2 %0, %1, %2;" : "=l"(d) : "l"(a), "l"(b)); return d;
}
__device__ __forceinline__ uint64_t dup2(float x) {
    uint64_t d; asm("mov.b64 %0, {%1, %1};" : "=l"(d) : "f"(x)); return d;
}
__device__ __forceinline__ uint64_t pack2(float lo, float hi) {
    uint64_t d; asm("mov.b64 %0, {%1, %2};" : "=l"(d) : "f"(lo), "f"(hi)); return d;
}

// TMA / mbarrier primitives (1D bulk, no tensormap needed)
__device__ __forceinline__ void mbar_init(uint32_t mbar, uint32_t cnt) {
    asm volatile("mbarrier.init.shared.b64 [%0], %1;" :: "r"(mbar), "r"(cnt) : "memory");
}
__device__ __forceinline__ void mbar_expect(uint32_t mbar, uint32_t bytes) {
    asm volatile("mbarrier.arrive.expect_tx.shared.b64 _, [%0], %1;"
                 :: "r"(mbar), "r"(bytes) : "memory");
}
__device__ __forceinline__ void mbar_wait(uint32_t mbar, uint32_t parity) {
    asm volatile(
        "{\n\t.reg .pred P;\n"
        "WL_%=:\n\t"
        "mbarrier.try_wait.parity.shared.b64 P, [%0], %1, 0x989680;\n\t"
        "@P bra WD_%=;\n\t"
        "bra WL_%=;\n"
        "WD_%=:\n\t}"
        :: "r"(mbar), "r"(parity) : "memory");
}
__device__ __forceinline__ void bulk_ld(uint32_t sdst, const void* gsrc,
                                        uint32_t bytes, uint32_t mbar) {
    asm volatile("cp.async.bulk.shared::cta.global.mbarrier::complete_tx::bytes "
                 "[%0], [%1], %2, [%3];"
                 :: "r"(sdst), "l"(gsrc), "r"(bytes), "r"(mbar) : "memory");
}
__device__ __forceinline__ void bulk_st(void* gdst, uint32_t ssrc, uint32_t bytes) {
    asm volatile("cp.async.bulk.global.shared::cta.bulk_group [%0], [%1], %2;"
                 :: "l"(gdst), "r"(ssrc), "r"(bytes) : "memory");
}

// smem carve (bytes)
#define SM_P   0                 // p row staging, 32KB
#define SM_C   32768             // c row staging (for concat TMA store), 32KB
#define SM_WQ  65536             // wqT 2KB
#define SM_WK  (SM_WQ + 2048)
#define SM_WV  (SM_WK + 2048)
#define SM_WY  (SM_WV + 2048)    // wy 2KB
#define SM_BQ  (SM_WY + 2048)
#define SM_BK  (SM_BQ + 64)
#define SM_BV  (SM_BK + 64)
#define SM_BY  (SM_BV + 64)
#define SM_RED (SM_BY + 128)     // 4 warps x 8 u64 = 256B
#define SM_MB  (SM_RED + 256)    // mbarrier, 8B
#define SM_TOT (SM_MB + 64)

// R6 compute core + TMA phase 1: p and c rows arrive via cp.async.bulk
// (tma pipe, zero l1tex), concat copy leaves via bulk store, compute reads
// c from L2 (TMA load just warmed it) and p from smem.
__global__ void __launch_bounds__(NT, 3) cross_attn_kernel(
    const float* __restrict__ cin, const float* __restrict__ pin,
    const float* __restrict__ Wq,  const float* __restrict__ bq,
    const float* __restrict__ Wk,  const float* __restrict__ bk,
    const float* __restrict__ Wv,  const float* __restrict__ bv,
    const float* __restrict__ Wy,  const float* __restrict__ by,
    float* __restrict__ out)
{
    extern __shared__ __align__(16) char smraw[];
    float2*   wqT  = (float2*)(smraw + SM_WQ);   // [c][o2] natural o-pairs
    float2*   wkT  = (float2*)(smraw + SM_WK);
    float2*   wvT  = (float2*)(smraw + SM_WV);
    float4*   wy_s = (float4*)(smraw + SM_WY);
    float2*   bq2  = (float2*)(smraw + SM_BQ);
    float2*   bk2  = (float2*)(smraw + SM_BK);
    float2*   bv2  = (float2*)(smraw + SM_BV);
    float*    by_s = (float*) (smraw + SM_BY);
    uint64_t* red  = (uint64_t*)(smraw + SM_RED);
    const uint32_t smbase = (uint32_t)__cvta_generic_to_shared(smraw);
    const uint32_t mbar   = smbase + SM_MB;

    const int tid = threadIdx.x;
    const int h = blockIdx.x & (IMG_H - 1);
    const int b = blockIdx.x >> 8;
    const size_t base = (size_t)b * CH_IN * CHS + (size_t)h * IMG_W;
    float* outc = out + (size_t)b * 2 * CH_IN * CHS + (size_t)CH_IN * CHS
                      + (size_t)h * IMG_W;       // concat(c) half

    // ---- weight setup (transpose to [c][o2] pair layout) ----
#pragma unroll
    for (int s = 0; s < 2; s++) {
        int i = tid * 2 + s;                     // 0..255
        int c = i >> 3, o2 = i & 7;
        wqT[i] = make_float2(Wq[(2*o2)*CH_IN + c], Wq[(2*o2+1)*CH_IN + c]);
        wkT[i] = make_float2(Wk[(2*o2)*CH_IN + c], Wk[(2*o2+1)*CH_IN + c]);
        wvT[i] = make_float2(Wv[(2*o2)*CH_IN + c], Wv[(2*o2+1)*CH_IN + c]);
    }
    wy_s[tid] = ((const float4*)Wy)[tid];
    if (tid < 8) {
        bq2[tid] = make_float2(bq[2*tid], bq[2*tid+1]);
        bk2[tid] = make_float2(bk[2*tid], bk[2*tid+1]);
        bv2[tid] = make_float2(bv[2*tid], bv[2*tid+1]);
    }
    if (tid < CH_IN) by_s[tid] = by[tid];
    if (tid == 0) mbar_init(mbar, 1);
    __syncthreads();

    // ---- TMA phase 1: pull c row + p row (64KB total) onto the tma pipe ----
    if (tid == 0) {
        mbar_expect(mbar, 2 * CH_IN * ROWB);     // 65536 bytes
#pragma unroll 4
        for (int ch = 0; ch < CH_IN; ch++) {
            bulk_ld(smbase + SM_P + ch * ROWB, pin + base + (size_t)ch * CHS,
                    ROWB, mbar);
            bulk_ld(smbase + SM_C + ch * ROWB, cin + base + (size_t)ch * CHS,
                    ROWB, mbar);
        }
    }
    mbar_wait(mbar, 0);                          // all threads

    // concat copy: fire-and-forget bulk stores from the staged c row
    if (tid == 0) {
#pragma unroll 4
        for (int ch = 0; ch < CH_IN; ch++)
            bulk_st(outc + (size_t)ch * CHS, smbase + SM_C + ch * ROWB, ROWB);
        asm volatile("cp.async.bulk.commit_group;" ::: "memory");
    }

    // ---------------- q,k projection (R6 core) ----------------
    const float2* cp2 = (const float2*)(cin + base);   // L2-hot (TMA warmed it)
    const float2* sp2 = (const float2*)(smraw + SM_P); // + ch*128 + tid

    uint64_t q[2][8], k[2][8];        // [px][o2] packed (o 2o2, 2o2+1)
#pragma unroll
    for (int o2 = 0; o2 < 8; o2++) {
        F2U tq; tq.f = bq2[o2]; q[0][o2] = tq.u; q[1][o2] = tq.u;
        F2U tk; tk.f = bk2[o2]; k[0][o2] = tk.u; k[1][o2] = tk.u;
    }

#pragma unroll
    for (int c4 = 0; c4 < CH_IN / 4; c4++) {
        float2 cv[4], pv[4];
#pragma unroll
        for (int j = 0; j < 4; j++) {
            int ch = c4 * 4 + j;
            cv[j] = cp2[(size_t)ch * CHS2 + tid];
            pv[j] = sp2[ch * 128 + tid];
        }
#pragma unroll
        for (int j = 0; j < 4; j++) {
            const int ch = c4 * 4 + j;
            const ulonglong2* wq2 = (const ulonglong2*)&wqT[ch * 8];
            const ulonglong2* wk2 = (const ulonglong2*)&wkT[ch * 8];
            uint64_t cd0 = dup2(cv[j].x), cd1 = dup2(cv[j].y);
            uint64_t pd0 = dup2(pv[j].x), pd1 = dup2(pv[j].y);
#pragma unroll
            for (int m = 0; m < 4; m++) {        // 2 o-pairs per LDS.128
                ulonglong2 a = wq2[m];
                fma2(q[0][2*m+0], a.x, cd0); fma2(q[0][2*m+1], a.y, cd0);
                fma2(q[1][2*m+0], a.x, cd1); fma2(q[1][2*m+1], a.y, cd1);
                ulonglong2 bm = wk2[m];
                fma2(k[0][2*m+0], bm.x, pd0); fma2(k[0][2*m+1], bm.y, pd0);
                fma2(k[1][2*m+0], bm.x, pd1); fma2(k[1][2*m+1], bm.y, pd1);
            }
        }
    }

    // exp(q*k). No max-subtraction: |q*k| O(1..10); fp32 exp safe, identical
    // after normalization.
    uint64_t e[2][8];
#pragma unroll
    for (int px = 0; px < 2; px++)
#pragma unroll
        for (int o2 = 0; o2 < 8; o2++) {
            F2U pr; pr.u = mul2(q[px][o2], k[px][o2]);
            e[px][o2] = pack2(__expf(pr.f.x), __expf(pr.f.y));
        }

    // ---------------- softmax over width (block reduction) ----------------
    const int lane = tid & 31;
    const int wrp  = tid >> 5;
#pragma unroll
    for (int o2 = 0; o2 < 8; o2++) {
        uint64_t s = add2(e[0][o2], e[1][o2]);
#pragma unroll
        for (int d = 16; d > 0; d >>= 1)
            s = add2(s, __shfl_xor_sync(0xffffffffu, (unsigned long long)s, d));
        if (lane == 0) red[wrp * 8 + o2] = s;
    }
    __syncthreads();

#pragma unroll
    for (int o2 = 0; o2 < 8; o2++) {
        F2U tot; tot.u = add2(add2(red[0*8+o2], red[1*8+o2]),
                              add2(red[2*8+o2], red[3*8+o2]));
        uint64_t inv = pack2(__frcp_rn(tot.f.x), __frcp_rn(tot.f.y));
        e[0][o2] = mul2(e[0][o2], inv);          // fold 1/sum into e
        e[1][o2] = mul2(e[1][o2], inv);
    }

    // ---------------- v projection (p from smem) ----------------
    {
        uint64_t v[2][8];
#pragma unroll
        for (int o2 = 0; o2 < 8; o2++) {
            F2U tv; tv.f = bv2[o2]; v[0][o2] = tv.u; v[1][o2] = tv.u;
        }
#pragma unroll
        for (int c4 = 0; c4 < CH_IN / 4; c4++) {
            float2 pv[4];
#pragma unroll
            for (int j = 0; j < 4; j++)
                pv[j] = sp2[(c4 * 4 + j) * 128 + tid];
#pragma unroll
            for (int j = 0; j < 4; j++) {
                const int ch = c4 * 4 + j;
                const ulonglong2* wv2 = (const ulonglong2*)&wvT[ch * 8];
                uint64_t pd0 = dup2(pv[j].x), pd1 = dup2(pv[j].y);
#pragma unroll
                for (int m = 0; m < 4; m++) {
                    ulonglong2 a = wv2[m];
                    fma2(v[0][2*m+0], a.x, pd0); fma2(v[0][2*m+1], a.y, pd0);
                    fma2(v[1][2*m+0], a.x, pd1); fma2(v[1][2*m+1], a.y, pd1);
                }
            }
        }
#pragma unroll
        for (int px = 0; px < 2; px++)
#pragma unroll
            for (int o2 = 0; o2 < 8; o2++)
                e[px][o2] = mul2(e[px][o2], v[px][o2]);   // y = softmax * v
    }

    // ---------------- output conv1x1 ----------------
    float2* oy2 = (float2*)(out + (size_t)b * 2 * CH_IN * CHS + (size_t)h * IMG_W);
    const ulonglong2* wyu2 = (const ulonglong2*)wy_s;     // 4 per ic, o-pairs
#pragma unroll
    for (int ic = 0; ic < CH_IN; ic++) {
        uint64_t acc0 = pack2(by_s[ic], 0.f);
        uint64_t acc1 = acc0;
#pragma unroll
        for (int m = 0; m < 4; m++) {
            ulonglong2 w = wyu2[ic * 4 + m];              // o-pairs (2m, 2m+1)
            fma2(acc0, w.x, e[0][2*m+0]); fma2(acc0, w.y, e[0][2*m+1]);
            fma2(acc1, w.x, e[1][2*m+0]); fma2(acc1, w.y, e[1][2*m+1]);
        }
        F2U r0, r1; r0.u = acc0; r1.u = acc1;
        oy2[(size_t)ic * CHS2 + tid] = make_float2(r0.f.x + r0.f.y,
                                                   r1.f.x + r1.f.y);
    }

    // drain the concat bulk stores before smem is torn down
    if (tid == 0)
        asm volatile("cp.async.bulk.wait_group 0;" ::: "memory");
}

extern "C" void kernel_launch(void* const* d_in, const int* in_sizes, int n_in,
                              void* d_out, int out_size)
{
    cudaFuncSetAttribute(cross_attn_kernel,
                         cudaFuncAttributeMaxDynamicSharedMemorySize, SM_TOT);
    cross_attn_kernel<<<NB * IMG_H, NT, SM_TOT>>>(
        (const float*)d_in[0],  // c
        (const float*)d_in[1],  // p
        (const float*)d_in[2],  // Wq
        (const float*)d_in[3],  // bq
        (const float*)d_in[4],  // Wk
        (const float*)d_in[5],  // bk
        (const float*)d_in[6],  // Wv
        (const float*)d_in[7],  // bv
        (const float*)d_in[8],  // Wy
        (const float*)d_in[9],  // by
        (float*)d_out);
}

// round 16
// speedup vs baseline: 1.3385x; 1.1075x over previous
#include <cuda_runtime.h>
#include <cstdint>

#define CH_IN 32
#define CH_Y  16
#define IMG_H 256
#define IMG_W 256
#define NB    16
#define CHS   (IMG_H * IMG_W)   // channel stride (elements)
#define CHS2  (CHS / 2)
#define NT    128               // one (b,h) row; thread = px-pair, full 16 o
#define ROWB  (IMG_W * 4)       // bytes per channel strip (1KB)

union F2U { float2 f; uint64_t u; };

// sm_103a packed dual-fp32 ops
__device__ __forceinline__ void fma2(uint64_t& d, uint64_t a, uint64_t b) {
    asm("fma.rn.f32x2 %0, %1, %2, %0;" : "+l"(d) : "l"(a), "l"(b));
}
__device__ __forceinline__ uint64_t mul2(uint64_t a, uint64_t b) {
    uint64_t d; asm("mul.rn.f32x2 %0, %1, %2;" : "=l"(d) : "l"(a), "l"(b)); return d;
}
__device__ __forceinline__ uint64_t add2(uint64_t a, uint64_t b) {
    uint64_t d; asm("add.rn.f32x2 %0, %1, %2;" : "=l"(d) : "l"(a), "l"(b)); return d;
}
__device__ __forceinline__ uint64_t dup2(float x) {
    uint64_t d; asm("mov.b64 %0, {%1, %1};" : "=l"(d) : "f"(x)); return d;
}
__device__ __forceinline__ uint64_t pack2(float lo, float hi) {
    uint64_t d; asm("mov.b64 %0, {%1, %2};" : "=l"(d) : "f"(lo), "f"(hi)); return d;
}

// TMA / mbarrier primitives (1D bulk, no tensormap needed)
__device__ __forceinline__ void mbar_init(uint32_t mbar, uint32_t cnt) {
    asm volatile("mbarrier.init.shared.b64 [%0], %1;" :: "r"(mbar), "r"(cnt) : "memory");
}
__device__ __forceinline__ void mbar_expect(uint32_t mbar, uint32_t bytes) {
    asm volatile("mbarrier.arrive.expect_tx.shared.b64 _, [%0], %1;"
                 :: "r"(mbar), "r"(bytes) : "memory");
}
__device__ __forceinline__ void mbar_wait(uint32_t mbar, uint32_t parity) {
    asm volatile(
        "{\n\t.reg .pred P;\n"
        "WL_%=:\n\t"
        "mbarrier.try_wait.parity.shared.b64 P, [%0], %1, 0x989680;\n\t"
        "@P bra WD_%=;\n\t"
        "bra WL_%=;\n"
        "WD_%=:\n\t}"
        :: "r"(mbar), "r"(parity) : "memory");
}
__device__ __forceinline__ void bulk_ld(uint32_t sdst, const void* gsrc,
                                        uint32_t bytes, uint32_t mbar) {
    asm volatile("cp.async.bulk.shared::cta.global.mbarrier::complete_tx::bytes "
                 "[%0], [%1], %2, [%3];"
                 :: "r"(sdst), "l"(gsrc), "r"(bytes), "r"(mbar) : "memory");
}

// smem carve (bytes): p staging + weights only (~41KB -> 4 blocks/SM)
#define SM_P   0                 // p row staging, 32KB
#define SM_WQ  32768             // wqT 2KB
#define SM_WK  (SM_WQ + 2048)
#define SM_WV  (SM_WK + 2048)
#define SM_WY  (SM_WV + 2048)    // wy 2KB
#define SM_BQ  (SM_WY + 2048)
#define SM_BK  (SM_BQ + 64)
#define SM_BV  (SM_BK + 64)
#define SM_BY  (SM_BV + 64)
#define SM_RED (SM_BY + 128)     // 4 warps x 8 u64 = 256B
#define SM_MB  (SM_RED + 256)    // mbarrier, 8B
#define SM_TOT (SM_MB + 64)

// R6 compute core; p row arrives via cp.async.bulk (tma pipe, no l1tex);
// c streams through registers in the q-pass with concat STG write-through.
__global__ void __launch_bounds__(NT, 4) cross_attn_kernel(
    const float* __restrict__ cin, const float* __restrict__ pin,
    const float* __restrict__ Wq,  const float* __restrict__ bq,
    const float* __restrict__ Wk,  const float* __restrict__ bk,
    const float* __restrict__ Wv,  const float* __restrict__ bv,
    const float* __restrict__ Wy,  const float* __restrict__ by,
    float* __restrict__ out)
{
    extern __shared__ __align__(16) char smraw[];
    float2*   wqT  = (float2*)(smraw + SM_WQ);   // [c][o2] natural o-pairs
    float2*   wkT  = (float2*)(smraw + SM_WK);
    float2*   wvT  = (float2*)(smraw + SM_WV);
    float4*   wy_s = (float4*)(smraw + SM_WY);
    float2*   bq2  = (float2*)(smraw + SM_BQ);
    float2*   bk2  = (float2*)(smraw + SM_BK);
    float2*   bv2  = (float2*)(smraw + SM_BV);
    float*    by_s = (float*) (smraw + SM_BY);
    uint64_t* red  = (uint64_t*)(smraw + SM_RED);
    const uint32_t smbase = (uint32_t)__cvta_generic_to_shared(smraw);
    const uint32_t mbar   = smbase + SM_MB;

    const int tid = threadIdx.x;
    const int h = blockIdx.x & (IMG_H - 1);
    const int b = blockIdx.x >> 8;
    const size_t base = (size_t)b * CH_IN * CHS + (size_t)h * IMG_W;

    // ---- kick off TMA p-load first so it overlaps weight setup ----
    if (tid == 0) {
        mbar_init(mbar, 1);
        asm volatile("fence.proxy.async.shared::cta;" ::: "memory");
        mbar_expect(mbar, CH_IN * ROWB);         // 32768 bytes
#pragma unroll 4
        for (int ch = 0; ch < CH_IN; ch++)
            bulk_ld(smbase + SM_P + ch * ROWB, pin + base + (size_t)ch * CHS,
                    ROWB, mbar);
    }

    // ---- weight setup (transpose to [c][o2] pair layout) ----
#pragma unroll
    for (int s = 0; s < 2; s++) {
        int i = tid * 2 + s;                     // 0..255
        int c = i >> 3, o2 = i & 7;
        wqT[i] = make_float2(Wq[(2*o2)*CH_IN + c], Wq[(2*o2+1)*CH_IN + c]);
        wkT[i] = make_float2(Wk[(2*o2)*CH_IN + c], Wk[(2*o2+1)*CH_IN + c]);
        wvT[i] = make_float2(Wv[(2*o2)*CH_IN + c], Wv[(2*o2+1)*CH_IN + c]);
    }
    wy_s[tid] = ((const float4*)Wy)[tid];
    if (tid < 8) {
        bq2[tid] = make_float2(bq[2*tid], bq[2*tid+1]);
        bk2[tid] = make_float2(bk[2*tid], bk[2*tid+1]);
        bv2[tid] = make_float2(bv[2*tid], bv[2*tid+1]);
    }
    if (tid < CH_IN) by_s[tid] = by[tid];
    __syncthreads();                             // weights visible to all
    mbar_wait(mbar, 0);                          // p row staged

    // ---------------- q,k projection: c streams, concat write-through -------
    const float2* cp2 = (const float2*)(cin + base);   // + ch*CHS2 + tid
    const float2* sp2 = (const float2*)(smraw + SM_P); // + ch*128 + tid
    float2* oy2 = (float2*)(out + (size_t)b * 2 * CH_IN * CHS + (size_t)h * IMG_W);
    float2* oc2 = oy2 + (size_t)CH_IN * CHS2;          // concat(c) half

    uint64_t q[2][8], k[2][8];        // [px][o2] packed (o 2o2, 2o2+1)
#pragma unroll
    for (int o2 = 0; o2 < 8; o2++) {
        F2U tq; tq.f = bq2[o2]; q[0][o2] = tq.u; q[1][o2] = tq.u;
        F2U tk; tk.f = bk2[o2]; k[0][o2] = tk.u; k[1][o2] = tk.u;
    }

#pragma unroll
    for (int c4 = 0; c4 < CH_IN / 4; c4++) {
        float2 cv[4], pv[4];
#pragma unroll
        for (int j = 0; j < 4; j++) {
            int ch = c4 * 4 + j;
            cv[j] = cp2[(size_t)ch * CHS2 + tid];      // DRAM stream (first touch)
            pv[j] = sp2[ch * 128 + tid];
        }
#pragma unroll
        for (int j = 0; j < 4; j++)                    // concat write-through
            oc2[(size_t)(c4 * 4 + j) * CHS2 + tid] = cv[j];
#pragma unroll
        for (int j = 0; j < 4; j++) {
            const int ch = c4 * 4 + j;
            const ulonglong2* wq2 = (const ulonglong2*)&wqT[ch * 8];
            const ulonglong2* wk2 = (const ulonglong2*)&wkT[ch * 8];
            uint64_t cd0 = dup2(cv[j].x), cd1 = dup2(cv[j].y);
            uint64_t pd0 = dup2(pv[j].x), pd1 = dup2(pv[j].y);
#pragma unroll
            for (int m = 0; m < 4; m++) {              // 2 o-pairs per LDS.128
                ulonglong2 a = wq2[m];
                fma2(q[0][2*m+0], a.x, cd0); fma2(q[0][2*m+1], a.y, cd0);
                fma2(q[1][2*m+0], a.x, cd1); fma2(q[1][2*m+1], a.y, cd1);
                ulonglong2 bm = wk2[m];
                fma2(k[0][2*m+0], bm.x, pd0); fma2(k[0][2*m+1], bm.y, pd0);
                fma2(k[1][2*m+0], bm.x, pd1); fma2(k[1][2*m+1], bm.y, pd1);
            }
        }
    }

    // exp(q*k). No max-subtraction: |q*k| O(1..10); fp32 exp safe, identical
    // after normalization.
    uint64_t e[2][8];
#pragma unroll
    for (int px = 0; px < 2; px++)
#pragma unroll
        for (int o2 = 0; o2 < 8; o2++) {
            F2U pr; pr.u = mul2(q[px][o2], k[px][o2]);
            e[px][o2] = pack2(__expf(pr.f.x), __expf(pr.f.y));
        }

    // ---------------- softmax over width (block reduction) ----------------
    const int lane = tid & 31;
    const int wrp  = tid >> 5;
#pragma unroll
    for (int o2 = 0; o2 < 8; o2++) {
        uint64_t s = add2(e[0][o2], e[1][o2]);
#pragma unroll
        for (int d = 16; d > 0; d >>= 1)
            s = add2(s, __shfl_xor_sync(0xffffffffu, (unsigned long long)s, d));
        if (lane == 0) red[wrp * 8 + o2] = s;
    }
    __syncthreads();

#pragma unroll
    for (int o2 = 0; o2 < 8; o2++) {
        F2U tot; tot.u = add2(add2(red[0*8+o2], red[1*8+o2]),
                              add2(red[2*8+o2], red[3*8+o2]));
        uint64_t inv = pack2(__frcp_rn(tot.f.x), __frcp_rn(tot.f.y));
        e[0][o2] = mul2(e[0][o2], inv);          // fold 1/sum into e
        e[1][o2] = mul2(e[1][o2], inv);
    }

    // ---------------- v projection (p from smem) ----------------
    {
        uint64_t v[2][8];
#pragma unroll
        for (int o2 = 0; o2 < 8; o2++) {
            F2U tv; tv.f = bv2[o2]; v[0][o2] = tv.u; v[1][o2] = tv.u;
        }
#pragma unroll
        for (int c4 = 0; c4 < CH_IN / 4; c4++) {
            float2 pv[4];
#pragma unroll
            for (int j = 0; j < 4; j++)
                pv[j] = sp2[(c4 * 4 + j) * 128 + tid];
#pragma unroll
            for (int j = 0; j < 4; j++) {
                const int ch = c4 * 4 + j;
                const ulonglong2* wv2 = (const ulonglong2*)&wvT[ch * 8];
                uint64_t pd0 = dup2(pv[j].x), pd1 = dup2(pv[j].y);
#pragma unroll
                for (int m = 0; m < 4; m++) {
                    ulonglong2 a = wv2[m];
                    fma2(v[0][2*m+0], a.x, pd0); fma2(v[0][2*m+1], a.y, pd0);
                    fma2(v[1][2*m+0], a.x, pd1); fma2(v[1][2*m+1], a.y, pd1);
                }
            }
        }
#pragma unroll
        for (int px = 0; px < 2; px++)
#pragma unroll
            for (int o2 = 0; o2 < 8; o2++)
                e[px][o2] = mul2(e[px][o2], v[px][o2]);   // y = softmax * v
    }

    // ---------------- output conv1x1 ----------------
    const ulonglong2* wyu2 = (const ulonglong2*)wy_s;     // 4 per ic, o-pairs
#pragma unroll
    for (int ic = 0; ic < CH_IN; ic++) {
        uint64_t acc0 = pack2(by_s[ic], 0.f);
        uint64_t acc1 = acc0;
#pragma unroll
        for (int m = 0; m < 4; m++) {
            ulonglong2 w = wyu2[ic * 4 + m];              // o-pairs (2m, 2m+1)
            fma2(acc0, w.x, e[0][2*m+0]); fma2(acc0, w.y, e[0][2*m+1]);
            fma2(acc1, w.x, e[1][2*m+0]); fma2(acc1, w.y, e[1][2*m+1]);
        }
        F2U r0, r1; r0.u = acc0; r1.u = acc1;
        oy2[(size_t)ic * CHS2 + tid] = make_float2(r0.f.x + r0.f.y,
                                                   r1.f.x + r1.f.y);
    }
}

extern "C" void kernel_launch(void* const* d_in, const int* in_sizes, int n_in,
                              void* d_out, int out_size)
{
    cudaFuncSetAttribute(cross_attn_kernel,
                         cudaFuncAttributeMaxDynamicSharedMemorySize, SM_TOT);
    cross_attn_kernel<<<NB * IMG_H, NT, SM_TOT>>>(
        (const float*)d_in[0],  // c
        (const float*)d_in[1],  // p
        (const float*)d_in[2],  // Wq
        (const float*)d_in[3],  // bq
        (const float*)d_in[4],  // Wk
        (const float*)d_in[5],  // bk
        (const float*)d_in[6],  // Wv
        (const float*)d_in[7],  // bv
        (const float*)d_in[8],  // Wy
        (const float*)d_in[9],  // by
        (float*)d_out);
}